// round 1
// baseline (speedup 1.0000x reference)
#include <cuda_runtime.h>
#include <math.h>

#define BB 8
#define SS 128
#define DD 256
#define HH 8
#define TT 129
#define HDIM 32

// Scratch (no allocations allowed)
__device__ float g_A [BB*SS*DD];   // desc @ We1[:256]
__device__ float g_Bm[BB*SS*DD];   // desc @ We1[256:]
__device__ float g_V [BB*TT*DD];   // nv @ Wv + bv
__device__ float g_u [DD*HH];      // We2 folded with wa_e
__device__ float g_wq[DD*HH];      // Wq folded with wa_q
__device__ float g_wk[DD*HH];      // Wk folded with wa_k
__device__ float g_qa[BB*HH*TT];
__device__ float g_ka[BB*HH*TT];
__device__ float g_beff[3*HH];     // [0:8)=bq_eff [8:16)=bk_eff [16:24)=be2_eff

// ---------------------------------------------------------------------------
// Fold wa into the projection matrices: w_eff[d][h] = sum_e W[d][h*32+e]*wa_seg[e]
__global__ void k_setup(const float* __restrict__ Wq, const float* __restrict__ Wk,
                        const float* __restrict__ We2, const float* __restrict__ wa,
                        const float* __restrict__ bq, const float* __restrict__ bk,
                        const float* __restrict__ be2) {
    __shared__ float wa_s[96];
    int d = threadIdx.x;             // 0..255
    if (d < 96) wa_s[d] = wa[d];
    __syncthreads();
    #pragma unroll
    for (int h = 0; h < 8; h++) {
        float s1 = 0.f, s2 = 0.f, s3 = 0.f;
        #pragma unroll 8
        for (int e = 0; e < 32; e++) {
            int c = h * 32 + e;
            s1 += Wq [d * 256 + c] * wa_s[e];
            s2 += Wk [d * 256 + c] * wa_s[32 + e];
            s3 += We2[d * 256 + c] * wa_s[64 + e];
        }
        g_wq[d * 8 + h] = s1;
        g_wk[d * 8 + h] = s2;
        g_u [d * 8 + h] = s3;
    }
    if (d < 24) {
        int h = d & 7, which = d >> 3;
        const float* bp = (which == 0) ? bq : (which == 1) ? bk : be2;
        int wo = which * 32;
        float s = 0.f;
        for (int e = 0; e < 32; e++) s += bp[h * 32 + e] * wa_s[wo + e];
        g_beff[d] = s;
    }
}

// ---------------------------------------------------------------------------
// C[M,256] = X[M,256] @ W[(wRowOff)+256 x 256] (+bias). mode selects dest.
__global__ void __launch_bounds__(256) k_gemm(const float* __restrict__ X,
                                              const float* __restrict__ W,
                                              const float* __restrict__ bias,
                                              int M, int wRowOff, int mode) {
    float* C = (mode == 0) ? g_A : (mode == 1) ? g_Bm : g_V;
    __shared__ float Xs[64][33];
    __shared__ float Ws[32][64];
    int bm = blockIdx.x * 64, bn = blockIdx.y * 64;
    int tid = threadIdx.x;
    int tr = (tid >> 4) << 2;   // row base within tile
    int tc = (tid & 15) << 2;   // col base within tile
    float acc[4][4];
    #pragma unroll
    for (int r = 0; r < 4; r++)
        #pragma unroll
        for (int c = 0; c < 4; c++) acc[r][c] = 0.f;

    for (int k0 = 0; k0 < 256; k0 += 32) {
        #pragma unroll
        for (int l = 0; l < 8; l++) {
            int idx = tid + l * 256;
            int r = idx >> 5, c = idx & 31;
            int gr = bm + r;
            Xs[r][c] = (gr < M) ? X[gr * 256 + k0 + c] : 0.f;
            int r2 = idx >> 6, c2 = idx & 63;
            Ws[r2][c2] = W[(wRowOff + k0 + r2) * 256 + bn + c2];
        }
        __syncthreads();
        #pragma unroll
        for (int kk = 0; kk < 32; kk++) {
            float xv[4], wv[4];
            #pragma unroll
            for (int r = 0; r < 4; r++) xv[r] = Xs[tr + r][kk];
            #pragma unroll
            for (int c = 0; c < 4; c++) wv[c] = Ws[kk][tc + c];
            #pragma unroll
            for (int r = 0; r < 4; r++)
                #pragma unroll
                for (int c = 0; c < 4; c++) acc[r][c] += xv[r] * wv[c];
        }
        __syncthreads();
    }
    #pragma unroll
    for (int r = 0; r < 4; r++) {
        int gr = bm + tr + r;
        if (gr < M) {
            #pragma unroll
            for (int c = 0; c < 4; c++) {
                float v = acc[r][c];
                if (bias) v += bias[bn + tc + c];
                C[gr * 256 + bn + tc + c] = v;
            }
        }
    }
}

// ---------------------------------------------------------------------------
// qa[b,h,t] = nv[b,t] . wq_eff[:,h] + bq_eff[h]; same for ka. Warp per row.
__global__ void k_qaka(const float* __restrict__ nv) {
    int w = threadIdx.x >> 5, lane = threadIdx.x & 31;
    int row = blockIdx.x * 8 + w;              // 0..1031
    int b = row / TT, t = row % TT;
    float accq[8], acck[8];
    #pragma unroll
    for (int h = 0; h < 8; h++) { accq[h] = 0.f; acck[h] = 0.f; }
    #pragma unroll
    for (int k = 0; k < 8; k++) {
        int d = lane + 32 * k;
        float xv = nv[row * DD + d];
        #pragma unroll
        for (int h = 0; h < 8; h++) {
            accq[h] += xv * g_wq[d * 8 + h];
            acck[h] += xv * g_wk[d * 8 + h];
        }
    }
    #pragma unroll
    for (int h = 0; h < 8; h++) {
        #pragma unroll
        for (int off = 16; off; off >>= 1) {
            accq[h] += __shfl_xor_sync(0xffffffffu, accq[h], off);
            acck[h] += __shfl_xor_sync(0xffffffffu, acck[h], off);
        }
    }
    if (lane == 0) {
        #pragma unroll
        for (int h = 0; h < 8; h++) {
            g_qa[(b * HH + h) * TT + t] = accq[h] + g_beff[h];
            g_ka[(b * HH + h) * TT + t] = acck[h] + g_beff[8 + h];
        }
    }
}

// ---------------------------------------------------------------------------
// Main: per (b,i) block. Warp-per-j edge LN + dot-with-u, then per-head softmax.
__global__ void k_edge(const float* __restrict__ prior,
                       const float* __restrict__ be1,
                       const float* __restrict__ lng,
                       const float* __restrict__ lnb,
                       const float* __restrict__ ba_p,
                       float* __restrict__ out_attn) {
    int b = blockIdx.x / TT, i = blockIdx.x % TT;
    int tid = threadIdx.x, w = tid >> 5, lane = tid & 31;
    __shared__ float e_sh[HH][TT + 3];
    __shared__ float be1_sh[DD];
    be1_sh[tid] = be1[tid];

    // Constants in registers (identical per-lane across warps; L1 absorbs dup loads)
    float u_reg[8][8], gam[8], bet[8], av[8];
    #pragma unroll
    for (int k = 0; k < 8; k++) {
        int d = lane + 32 * k;
        gam[k] = lng[d];
        bet[k] = lnb[d];
        #pragma unroll
        for (int h = 0; h < 8; h++) u_reg[k][h] = g_u[d * 8 + h];
    }
    __syncthreads();

    const float* Arow = (i >= 1) ? &g_A[(b * SS + i - 1) * DD] : (const float*)0;
    #pragma unroll
    for (int k = 0; k < 8; k++) {
        int d = lane + 32 * k;
        av[k] = (i >= 1) ? (Arow[d] + be1_sh[d]) : 0.f;
    }

    // j in 1..128; warp w handles j = 1+w+8*jj
    for (int jj = 0; jj < 16; jj++) {
        int j = 1 + w + jj * 8;
        bool valid = (i == 0) || (j != i);
        float acc[8];
        #pragma unroll
        for (int h = 0; h < 8; h++) acc[h] = 0.f;
        if (valid) {
            const float* bm = &g_Bm[(b * SS + j - 1) * DD];
            float x[8];
            float s = 0.f, s2 = 0.f;
            if (i == 0) {
                const float* ar = &g_A[(b * SS + j - 1) * DD];
                #pragma unroll
                for (int k = 0; k < 8; k++) {
                    int d = lane + 32 * k;
                    float xv = ar[d] + be1_sh[d] + bm[d];
                    x[k] = xv; s += xv; s2 += xv * xv;
                }
            } else {
                #pragma unroll
                for (int k = 0; k < 8; k++) {
                    int d = lane + 32 * k;
                    float xv = av[k] + bm[d];
                    x[k] = xv; s += xv; s2 += xv * xv;
                }
            }
            #pragma unroll
            for (int off = 16; off; off >>= 1) {
                s  += __shfl_xor_sync(0xffffffffu, s,  off);
                s2 += __shfl_xor_sync(0xffffffffu, s2, off);
            }
            const float invD = 1.f / 256.f;
            float mu  = s * invD;
            float var = fmaxf(s2 * invD - mu * mu, 0.f);
            float rs  = rsqrtf(var + 1e-5f);
            #pragma unroll
            for (int k = 0; k < 8; k++) {
                float y = (x[k] - mu) * rs * gam[k] + bet[k];
                y = fmaxf(y, 0.f);
                #pragma unroll
                for (int h = 0; h < 8; h++) acc[h] += y * u_reg[k][h];
            }
            #pragma unroll
            for (int h = 0; h < 8; h++)
                #pragma unroll
                for (int off = 16; off; off >>= 1)
                    acc[h] += __shfl_xor_sync(0xffffffffu, acc[h], off);
        }
        if (lane == 0) {
            #pragma unroll
            for (int h = 0; h < 8; h++) e_sh[h][j] = acc[h];
        }
    }
    __syncthreads();

    // Softmax: warp w == head h over j = 0..128
    {
        int h = w;
        float base = g_qa[(b * HH + h) * TT + i] + ba_p[0] + g_beff[16 + h];
        const float* kap = &g_ka[(b * HH + h) * TT];
        const float* pr  = (i >= 1) ? &prior[((b * HH + h) * SS + (i - 1)) * SS] : (const float*)0;
        float lg[5];
        float mx = -3.4e38f;
        #pragma unroll
        for (int m = 0; m < 5; m++) {
            int j = lane + 32 * m;
            float L = -3.4e38f;
            if (j <= 128) {
                bool v2 = (j >= 1) && (i == 0 || j != i);
                if (!v2) L = -1e9f;
                else {
                    L = e_sh[h][j] + base + kap[j];
                    if (i >= 1) {
                        float p = pr[j - 1];
                        p = fminf(fmaxf(p, 1e-6f), 1.f - 1e-6f);
                        L += logf(p) - logf(1.f - p);
                    }
                }
            }
            lg[m] = L;
            mx = fmaxf(mx, L);
        }
        #pragma unroll
        for (int off = 16; off; off >>= 1)
            mx = fmaxf(mx, __shfl_xor_sync(0xffffffffu, mx, off));
        float sum = 0.f;
        #pragma unroll
        for (int m = 0; m < 5; m++) {
            int j = lane + 32 * m;
            if (j <= 128) { lg[m] = expf(lg[m] - mx); sum += lg[m]; }
            else lg[m] = 0.f;
        }
        #pragma unroll
        for (int off = 16; off; off >>= 1)
            sum += __shfl_xor_sync(0xffffffffu, sum, off);
        float inv = 1.f / sum;
        float* ao = out_attn + ((size_t)(b * HH + h) * TT + i) * TT;
        #pragma unroll
        for (int m = 0; m < 5; m++) {
            int j = lane + 32 * m;
            if (j <= 128) ao[j] = lg[m] * inv;
        }
    }
}

// ---------------------------------------------------------------------------
// ctx[b,h,i,:] = sum_j attn[b,h,i,j] * v[b,j, h*32:]; write as basis[b,i,h,:]
__global__ void k_ctx(const float* __restrict__ attn, float* __restrict__ out_basis) {
    int b = blockIdx.x / HH, h = blockIdx.x % HH;
    int tid = threadIdx.x, w = tid >> 5, lane = tid & 31;
    __shared__ float vsh[TT][HDIM];
    for (int idx = tid; idx < TT * HDIM; idx += 256) {
        int t = idx >> 5, d = idx & 31;
        vsh[t][d] = g_V[((size_t)b * TT + t) * DD + h * HDIM + d];
    }
    __syncthreads();
    for (int i = w; i < TT; i += 8) {
        const float* ar = attn + ((size_t)(b * HH + h) * TT + i) * TT;
        float a[5];
        #pragma unroll
        for (int m = 0; m < 5; m++) {
            int j = lane + 32 * m;
            a[m] = (j < TT) ? ar[j] : 0.f;
        }
        float acc = 0.f;
        #pragma unroll
        for (int m = 0; m < 4; m++) {
            #pragma unroll
            for (int l = 0; l < 32; l++) {
                float avv = __shfl_sync(0xffffffffu, a[m], l);
                acc += avv * vsh[m * 32 + l][lane];
            }
        }
        {
            float avv = __shfl_sync(0xffffffffu, a[4], 0);
            acc += avv * vsh[128][lane];
        }
        out_basis[(((size_t)b * TT + i) * HH + h) * HDIM + lane] = acc;
    }
}

// ---------------------------------------------------------------------------
extern "C" void kernel_launch(void* const* d_in, const int* in_sizes, int n_in,
                              void* d_out, int out_size) {
    const float* desc  = (const float*)d_in[0];
    const float* nv    = (const float*)d_in[1];
    const float* prior = (const float*)d_in[2];
    const float* Wq    = (const float*)d_in[3];
    const float* bq    = (const float*)d_in[4];
    const float* Wk    = (const float*)d_in[5];
    const float* bk    = (const float*)d_in[6];
    const float* Wv    = (const float*)d_in[7];
    const float* bv    = (const float*)d_in[8];
    const float* wa    = (const float*)d_in[9];
    const float* ba    = (const float*)d_in[10];
    const float* We1   = (const float*)d_in[11];
    const float* be1   = (const float*)d_in[12];
    const float* lng   = (const float*)d_in[13];
    const float* lnb   = (const float*)d_in[14];
    const float* We2   = (const float*)d_in[15];
    const float* be2   = (const float*)d_in[16];

    float* out      = (float*)d_out;
    float* out_attn = out + (size_t)BB * TT * HH * HDIM;

    k_setup<<<1, 256>>>(Wq, Wk, We2, wa, bq, bk, be2);
    k_gemm<<<dim3(16, 4), 256>>>(desc, We1, (const float*)0, BB * SS, 0,   0);  // A
    k_gemm<<<dim3(16, 4), 256>>>(desc, We1, (const float*)0, BB * SS, 256, 1);  // Bm
    k_gemm<<<dim3(17, 4), 256>>>(nv,   Wv,  bv,              BB * TT, 0,   2);  // V
    k_qaka<<<129, 256>>>(nv);
    k_edge<<<BB * TT, 256>>>(prior, be1, lng, lnb, ba, out_attn);
    k_ctx<<<BB * HH, 256>>>(out_attn, out);
}

// round 2
// speedup vs baseline: 1.2888x; 1.2888x over previous
#include <cuda_runtime.h>
#include <math.h>

#define BB 8
#define SS 128
#define DD 256
#define HH 8
#define TT 129
#define HDIM 32

// Scratch (no allocations allowed)
__device__ float g_A [BB*SS*DD];     // desc @ We1[:256] + be1
__device__ float g_Bm[BB*SS*DD];     // desc @ We1[256:]
__device__ float g_V [BB*TT*DD];     // nv @ Wv + bv
__device__ float g_u [DD*HH];        // We2 folded with wa_e
__device__ float g_wq[DD*HH];        // Wq folded with wa_q
__device__ float g_wk[DD*HH];        // Wk folded with wa_k
__device__ float g_qa[BB*HH*TT];     // includes bq_eff + ba + be2_eff
__device__ float g_ka[BB*HH*TT];     // includes bk_eff
__device__ float g_beff[3*HH];
__device__ float g_bias[BB*HH*SS*SS]; // log-odds prior bias

// ---------------------------------------------------------------------------
__global__ void k_setup(const float* __restrict__ Wq, const float* __restrict__ Wk,
                        const float* __restrict__ We2, const float* __restrict__ wa,
                        const float* __restrict__ bq, const float* __restrict__ bk,
                        const float* __restrict__ be2) {
    __shared__ float wa_s[96];
    int d = threadIdx.x;             // 0..255
    if (d < 96) wa_s[d] = wa[d];
    __syncthreads();
    #pragma unroll
    for (int h = 0; h < 8; h++) {
        float s1 = 0.f, s2 = 0.f, s3 = 0.f;
        #pragma unroll 8
        for (int e = 0; e < 32; e++) {
            int c = h * 32 + e;
            s1 += Wq [d * 256 + c] * wa_s[e];
            s2 += Wk [d * 256 + c] * wa_s[32 + e];
            s3 += We2[d * 256 + c] * wa_s[64 + e];
        }
        g_wq[d * 8 + h] = s1;
        g_wk[d * 8 + h] = s2;
        g_u [d * 8 + h] = s3;
    }
    if (d < 24) {
        int h = d & 7, which = d >> 3;
        const float* bp = (which == 0) ? bq : (which == 1) ? bk : be2;
        int wo = which * 32;
        float s = 0.f;
        for (int e = 0; e < 32; e++) s += bp[h * 32 + e] * wa_s[wo + e];
        g_beff[d] = s;
    }
}

// ---------------------------------------------------------------------------
__device__ __forceinline__ void gemm_tile(const float* __restrict__ X,
                                          const float* __restrict__ W,
                                          const float* __restrict__ bias,
                                          int M, int wRowOff, int bm, int bn,
                                          float* __restrict__ C,
                                          float* Xs, float* Ws) {
    int tid = threadIdx.x;
    int tr = (tid >> 4) << 2;
    int tc = (tid & 15) << 2;
    float acc[4][4];
    #pragma unroll
    for (int r = 0; r < 4; r++)
        #pragma unroll
        for (int c = 0; c < 4; c++) acc[r][c] = 0.f;

    for (int k0 = 0; k0 < 256; k0 += 32) {
        #pragma unroll
        for (int l = 0; l < 8; l++) {
            int idx = tid + l * 256;
            int r = idx >> 5, c = idx & 31;
            int gr = bm + r;
            Xs[r * 33 + c] = (gr < M) ? X[gr * 256 + k0 + c] : 0.f;
            int r2 = idx >> 6, c2 = idx & 63;
            Ws[r2 * 64 + c2] = W[(wRowOff + k0 + r2) * 256 + bn + c2];
        }
        __syncthreads();
        #pragma unroll
        for (int kk = 0; kk < 32; kk++) {
            float xv[4], wv[4];
            #pragma unroll
            for (int r = 0; r < 4; r++) xv[r] = Xs[(tr + r) * 33 + kk];
            #pragma unroll
            for (int c = 0; c < 4; c++) wv[c] = Ws[kk * 64 + tc + c];
            #pragma unroll
            for (int r = 0; r < 4; r++)
                #pragma unroll
                for (int c = 0; c < 4; c++) acc[r][c] = fmaf(xv[r], wv[c], acc[r][c]);
        }
        __syncthreads();
    }
    #pragma unroll
    for (int r = 0; r < 4; r++) {
        int gr = bm + tr + r;
        if (gr < M) {
            #pragma unroll
            for (int c = 0; c < 4; c++) {
                float v = acc[r][c];
                if (bias) v += bias[bn + tc + c];
                C[gr * 256 + bn + tc + c] = v;
            }
        }
    }
}

// One launch: A/Bm gemms (128 blocks), V gemm (68), qa/ka (129), prior bias (128)
__global__ void __launch_bounds__(256) k_fused(const float* __restrict__ desc,
                                               const float* __restrict__ nv,
                                               const float* __restrict__ prior,
                                               const float* __restrict__ We1,
                                               const float* __restrict__ be1,
                                               const float* __restrict__ Wv,
                                               const float* __restrict__ bv,
                                               const float* __restrict__ ba) {
    __shared__ float Xs[64 * 33];
    __shared__ float Ws[32 * 64];
    int t = blockIdx.x;
    int tid = threadIdx.x;
    if (t < 128) {
        // C_full[1024, 512] = desc @ [We1_top | We1_bot]
        int mt = t & 15, nt = t >> 4;       // nt 0..7
        bool isB = nt >= 4;
        gemm_tile(desc, We1, isB ? (const float*)0 : be1, BB * SS,
                  isB ? 256 : 0, mt * 64, (nt & 3) * 64,
                  isB ? g_Bm : g_A, Xs, Ws);
    } else if (t < 196) {
        int t2 = t - 128;
        int mt = t2 % 17, nt = t2 / 17;
        gemm_tile(nv, Wv, bv, BB * TT, 0, mt * 64, nt * 64, g_V, Xs, Ws);
    } else if (t < 325) {
        // qa / ka: warp per row
        int w = tid >> 5, lane = tid & 31;
        int row = (t - 196) * 8 + w;        // 0..1031
        int b = row / TT, tt = row % TT;
        float accq[8], acck[8];
        #pragma unroll
        for (int h = 0; h < 8; h++) { accq[h] = 0.f; acck[h] = 0.f; }
        #pragma unroll
        for (int k = 0; k < 8; k++) {
            int d = lane + 32 * k;
            float xv = nv[row * DD + d];
            #pragma unroll
            for (int h = 0; h < 8; h++) {
                accq[h] = fmaf(xv, g_wq[d * 8 + h], accq[h]);
                acck[h] = fmaf(xv, g_wk[d * 8 + h], acck[h]);
            }
        }
        #pragma unroll
        for (int h = 0; h < 8; h++) {
            #pragma unroll
            for (int off = 16; off; off >>= 1) {
                accq[h] += __shfl_xor_sync(0xffffffffu, accq[h], off);
                acck[h] += __shfl_xor_sync(0xffffffffu, acck[h], off);
            }
        }
        if (lane == 0) {
            float bav = ba[0];
            #pragma unroll
            for (int h = 0; h < 8; h++) {
                g_qa[(b * HH + h) * TT + tt] = accq[h] + g_beff[h] + bav + g_beff[16 + h];
                g_ka[(b * HH + h) * TT + tt] = acck[h] + g_beff[8 + h];
            }
        }
    } else {
        // prior -> clipped log-odds bias
        const int N = BB * HH * SS * SS;    // 1,048,576
        int base = (t - 325) * 256 + tid;
        for (int idx = base; idx < N; idx += 128 * 256) {
            float p = prior[idx];
            p = fminf(fmaxf(p, 1e-6f), 1.f - 1e-6f);
            g_bias[idx] = __logf(p) - __logf(1.f - p);
        }
    }
}

// ---------------------------------------------------------------------------
// Per (b,i) block (128 thr, warp-per-j). LN + head-dot + softmax -> attn.
__global__ void __launch_bounds__(128) k_edge(const float* __restrict__ lng,
                                              const float* __restrict__ lnb,
                                              float* __restrict__ out_attn) {
    int b = blockIdx.x / TT, i = blockIdx.x % TT;
    int tid = threadIdx.x, w = tid >> 5, lane = tid & 31;
    __shared__ float e_sh[HH][TT + 4];

    float u_reg[8][8], gam[8], bet[8], av[8];
    #pragma unroll
    for (int k = 0; k < 8; k++) {
        int d = lane + 32 * k;
        gam[k] = lng[d];
        bet[k] = lnb[d];
        #pragma unroll
        for (int h = 0; h < 8; h++) u_reg[k][h] = g_u[d * 8 + h];
    }
    if (i >= 1) {
        const float* ap = g_A + (b * SS + i - 1) * DD;
        #pragma unroll
        for (int k = 0; k < 8; k++) av[k] = ap[lane + 32 * k];
    }

    #pragma unroll 1
    for (int jj = 0; jj < 32; jj++) {
        int j = 1 + w + jj * 4;
        if (i == 0 || j != i) {
            int rj = b * SS + j - 1;
            const float* bmp = g_Bm + rj * DD;
            float x[8], s = 0.f, s2 = 0.f;
            if (i == 0) {
                const float* ap = g_A + rj * DD;
                #pragma unroll
                for (int k = 0; k < 8; k++) {
                    float xv = ap[lane + 32 * k] + bmp[lane + 32 * k];
                    x[k] = xv; s += xv; s2 = fmaf(xv, xv, s2);
                }
            } else {
                #pragma unroll
                for (int k = 0; k < 8; k++) {
                    float xv = av[k] + bmp[lane + 32 * k];
                    x[k] = xv; s += xv; s2 = fmaf(xv, xv, s2);
                }
            }
            #pragma unroll
            for (int off = 16; off; off >>= 1) {
                s  += __shfl_xor_sync(0xffffffffu, s,  off);
                s2 += __shfl_xor_sync(0xffffffffu, s2, off);
            }
            const float invD = 1.f / 256.f;
            float mu  = s * invD;
            float var = fmaxf(s2 * invD - mu * mu, 0.f);
            float rs  = rsqrtf(var + 1e-5f);
            float acc[8];
            #pragma unroll
            for (int h = 0; h < 8; h++) acc[h] = 0.f;
            #pragma unroll
            for (int k = 0; k < 8; k++) {
                float y = fmaxf((x[k] - mu) * rs * gam[k] + bet[k], 0.f);
                #pragma unroll
                for (int h = 0; h < 8; h++) acc[h] = fmaf(y, u_reg[k][h], acc[h]);
            }
            // Value-swapping butterfly: 9 shuffles, head h lands on lanes 4h..4h+3
            bool b4 = (lane & 16), b3 = (lane & 8), b2 = (lane & 4);
            float v0, v1, v2, v3;
            {
                float t0 = b4 ? acc[0] : acc[4];
                float t1 = b4 ? acc[1] : acc[5];
                float t2 = b4 ? acc[2] : acc[6];
                float t3 = b4 ? acc[3] : acc[7];
                v0 = (b4 ? acc[4] : acc[0]) + __shfl_xor_sync(0xffffffffu, t0, 16);
                v1 = (b4 ? acc[5] : acc[1]) + __shfl_xor_sync(0xffffffffu, t1, 16);
                v2 = (b4 ? acc[6] : acc[2]) + __shfl_xor_sync(0xffffffffu, t2, 16);
                v3 = (b4 ? acc[7] : acc[3]) + __shfl_xor_sync(0xffffffffu, t3, 16);
            }
            float w0, w1;
            {
                float t0 = b3 ? v0 : v2;
                float t1 = b3 ? v1 : v3;
                w0 = (b3 ? v2 : v0) + __shfl_xor_sync(0xffffffffu, t0, 8);
                w1 = (b3 ? v3 : v1) + __shfl_xor_sync(0xffffffffu, t1, 8);
            }
            float r;
            {
                float tsel = b2 ? w0 : w1;
                r = (b2 ? w1 : w0) + __shfl_xor_sync(0xffffffffu, tsel, 4);
            }
            r += __shfl_xor_sync(0xffffffffu, r, 2);
            r += __shfl_xor_sync(0xffffffffu, r, 1);
            if ((lane & 3) == 0) e_sh[lane >> 2][j] = r;
        }
    }
    __syncthreads();

    // Softmax: 4 warps, each handles heads w and w+4
    #pragma unroll
    for (int hh = 0; hh < 2; hh++) {
        int h = w + hh * 4;
        float base = g_qa[(b * HH + h) * TT + i];
        const float* kap = g_ka + (b * HH + h) * TT;
        const float* bi  = g_bias + (((size_t)(b * HH + h) * SS) + (i - 1)) * SS;
        float lg[5];
        float mx = -3.4e38f;
        #pragma unroll
        for (int m = 0; m < 5; m++) {
            int j = lane + 32 * m;
            float L = -3.4e38f;
            if (j <= 128) {
                bool ok = (j >= 1) && (i == 0 || j != i);
                if (!ok) L = -1e9f;
                else {
                    L = e_sh[h][j] + base + kap[j];
                    if (i >= 1) L += bi[j - 1];
                }
            }
            lg[m] = L;
            mx = fmaxf(mx, L);
        }
        #pragma unroll
        for (int off = 16; off; off >>= 1)
            mx = fmaxf(mx, __shfl_xor_sync(0xffffffffu, mx, off));
        float sum = 0.f;
        #pragma unroll
        for (int m = 0; m < 5; m++) {
            int j = lane + 32 * m;
            if (j <= 128) { lg[m] = __expf(lg[m] - mx); sum += lg[m]; }
            else lg[m] = 0.f;
        }
        #pragma unroll
        for (int off = 16; off; off >>= 1)
            sum += __shfl_xor_sync(0xffffffffu, sum, off);
        float inv = 1.f / sum;
        float* ao = out_attn + ((size_t)(b * HH + h) * TT + i) * TT;
        #pragma unroll
        for (int m = 0; m < 5; m++) {
            int j = lane + 32 * m;
            if (j <= 128) ao[j] = lg[m] * inv;
        }
    }
}

// ---------------------------------------------------------------------------
// ctx: block per (b,h,iq); iq splits i-range into 4 chunks.
__global__ void __launch_bounds__(256) k_ctx(const float* __restrict__ attn,
                                             float* __restrict__ out_basis) {
    int t = blockIdx.x;
    int iq = t & 3;
    int bh = t >> 2;
    int b = bh >> 3, h = bh & 7;
    int lo = (iq == 0) ? 0 : (33 + 32 * (iq - 1));
    int hi = (iq == 3) ? 129 : (33 + 32 * iq);
    int tid = threadIdx.x, w = tid >> 5, lane = tid & 31;
    __shared__ float vsh[TT][HDIM];
    for (int idx = tid; idx < TT * HDIM; idx += 256) {
        int tt2 = idx >> 5, d = idx & 31;
        vsh[tt2][d] = g_V[((size_t)b * TT + tt2) * DD + h * HDIM + d];
    }
    __syncthreads();
    for (int i = lo + w; i < hi; i += 8) {
        const float* ar = attn + ((size_t)(b * HH + h) * TT + i) * TT;
        float a[5];
        #pragma unroll
        for (int m = 0; m < 5; m++) {
            int j = lane + 32 * m;
            a[m] = (j < TT) ? ar[j] : 0.f;
        }
        float acc = 0.f;
        #pragma unroll
        for (int m = 0; m < 4; m++) {
            #pragma unroll
            for (int l = 0; l < 32; l++) {
                float avv = __shfl_sync(0xffffffffu, a[m], l);
                acc = fmaf(avv, vsh[m * 32 + l][lane], acc);
            }
        }
        {
            float avv = __shfl_sync(0xffffffffu, a[4], 0);
            acc = fmaf(avv, vsh[128][lane], acc);
        }
        out_basis[(((size_t)b * TT + i) * HH + h) * HDIM + lane] = acc;
    }
}

// ---------------------------------------------------------------------------
extern "C" void kernel_launch(void* const* d_in, const int* in_sizes, int n_in,
                              void* d_out, int out_size) {
    const float* desc  = (const float*)d_in[0];
    const float* nv    = (const float*)d_in[1];
    const float* prior = (const float*)d_in[2];
    const float* Wq    = (const float*)d_in[3];
    const float* bq    = (const float*)d_in[4];
    const float* Wk    = (const float*)d_in[5];
    const float* bk    = (const float*)d_in[6];
    const float* Wv    = (const float*)d_in[7];
    const float* bv    = (const float*)d_in[8];
    const float* wa    = (const float*)d_in[9];
    const float* ba    = (const float*)d_in[10];
    const float* We1   = (const float*)d_in[11];
    const float* be1   = (const float*)d_in[12];
    const float* lng   = (const float*)d_in[13];
    const float* lnb   = (const float*)d_in[14];
    const float* We2   = (const float*)d_in[15];
    const float* be2   = (const float*)d_in[16];

    float* out      = (float*)d_out;
    float* out_attn = out + (size_t)BB * TT * HH * HDIM;

    k_setup<<<1, 256>>>(Wq, Wk, We2, wa, bq, bk, be2);
    k_fused<<<453, 256>>>(desc, nv, prior, We1, be1, Wv, bv, ba);
    k_edge<<<BB * TT, 128>>>(lng, lnb, out_attn);
    k_ctx<<<BB * HH * 4, 256>>>(out_attn, out);
}